// round 10
// baseline (speedup 1.0000x reference)
#include <cuda_runtime.h>

#define BB     4
#define CC     32
#define HH     512
#define WW     512
#define NBOX   64
#define H_OUT_ 16
#define HW     (HH * WW)
#define MAX_W_ 192
#define CHALF  16
#define JSEG   64            // columns per work item
#define NSEG   3             // MAX_W / JSEG
#define NITEMS (BB * NBOX * H_OUT_ * 2 * NSEG)   // 24576 work items
#define NCTAS  (148 * 32)    // persistent grid: one wave, 32 CTAs/SM

// R9: persistent-CTA version of the R5 decomposition. 4736 CTAs of 64 threads
// each grid-stride over 24576 (bn, i, chan-half, j-segment) items: perfect
// load balance (item cost varies 12..64 valid columns), no wave-transition
// overhead. All output stores use __stcs (evict-first) so the 100MB output
// stream does not evict the L2-resident image lines -> the L1tex in-flight
// queue (the measured throughput ceiling) drains at L2-hit latency more often.
__global__ __launch_bounds__(JSEG) void roirotate_kernel(
    const float* __restrict__ img,      // (B, C, H, W)
    const float* __restrict__ boxes,    // (B, N, 5)
    float* __restrict__ out,            // (B, N, C, H_OUT, MAX_W)
    float* __restrict__ maskf,          // (B, N, MAX_W) as float, or null
    unsigned char* __restrict__ masku8) // (B, N, MAX_W) as u8, or null
{
    const int tid = threadIdx.x;

    for (int item = blockIdx.x; item < NITEMS; item += NCTAS) {
        // item = ((bn*H_OUT + i)*2 + half)*NSEG + jseg
        const int jseg = item % NSEG;
        int       r    = item / NSEG;
        const int half = r & 1;          r >>= 1;
        const int i    = r & (H_OUT_ - 1);
        const int bn   = r >> 4;
        const int b    = bn >> 6;
        const int j    = jseg * JSEG + tid;

        const float* bx = boxes + bn * 5;
        const float left = bx[0];
        const float top  = bx[1];
        const float bw   = bx[2] - left;
        const float bh   = bx[3] - top;

        // width = int32(bw/bh * H_OUT): IEEE-correct division so truncation
        // matches the JAX reference bit-exactly (mask is binary!)
        const int   width  = (int)(__fdiv_rn(bw, bh) * (float)H_OUT_);
        const float each_w = __fdiv_rn(bw, (float)(width - 1));
        const float each_h = __fdiv_rn(bh, (float)(H_OUT_ - 1));

        const bool valid = (j < width);

        // out index (32-bit: max 25,165,824 < 2^31)
        const int cstride = H_OUT_ * MAX_W_;
        const int obase   = (bn * CC + half * CHALF) * cstride + i * MAX_W_ + j;

        if (i == 0 && half == 0) {
            if (maskf)  __stcs(&maskf[bn * MAX_W_ + j], valid ? 1.0f : 0.0f);
            if (masku8) masku8[bn * MAX_W_ + j] = valid ? (unsigned char)1 : (unsigned char)0;
        }

        if (!valid) {
            #pragma unroll
            for (int cc = 0; cc < CHALF; cc++)
                __stcs(&out[obase + cc * cstride], 0.0f);
            continue;
        }

        const float x = (float)j * each_w + left;
        const float y = (float)i * each_h + top;
        int x0 = (int)floorf(x);
        int y0 = (int)floorf(y);
        int x1 = x0 + 1;
        int y1 = y0 + 1;
        x0 = max(0, min(x0, WW - 1));
        x1 = max(0, min(x1, WW - 1));
        y0 = max(0, min(y0, HH - 1));
        y1 = max(0, min(y1, HH - 1));

        const float wxl = (float)x1 - x;
        const float wxr = x - (float)x0;
        const float wyt = (float)y1 - y;
        const float wyb = y - (float)y0;

        const float wa = wxl * wyt;
        const float wb = wxl * wyb;
        const float wc = wxr * wyt;
        const float wd = wxr * wyb;

        const int o00 = y0 * WW + x0;
        const int dx  = x1 - x0;          // 0 or 1
        const int dy  = (y1 - y0) * WW;   // 0 or WW

        const float* p = img + b * (CC * HW) + (half * CHALF) * HW + o00;

        #pragma unroll
        for (int cc = 0; cc < CHALF; cc++) {
            const float ia = __ldg(p);
            const float ic = __ldg(p + dx);
            const float ib = __ldg(p + dy);
            const float id = __ldg(p + dy + dx);
            __stcs(&out[obase + cc * cstride],
                   ia * wa + ib * wb + ic * wc + id * wd);
            p += HW;
        }
    }
}

extern "C" void kernel_launch(void* const* d_in, const int* in_sizes, int n_in,
                              void* d_out, int out_size)
{
    const float* img   = (const float*)d_in[0];
    const float* boxes = (const float*)d_in[1];

    const long long R = (long long)BB * NBOX * CC * H_OUT_ * MAX_W_; // 25,165,824
    const long long M = (long long)BB * NBOX * MAX_W_;               // 49,152

    const dim3 grid(NCTAS);   // 4736 persistent CTAs (one wave at 32 CTA/SM)
    const dim3 block(JSEG);   // 64 threads

    if ((long long)out_size == R * 4 + M) {
        unsigned char* ob = (unsigned char*)d_out;
        roirotate_kernel<<<grid, block>>>(img, boxes, (float*)ob, nullptr, ob + R * 4);
    } else if ((long long)out_size >= R + M) {
        float* of = (float*)d_out;
        roirotate_kernel<<<grid, block>>>(img, boxes, of, of + R, nullptr);
    } else {
        float* of = (float*)d_out;
        roirotate_kernel<<<grid, block>>>(img, boxes, of, nullptr, nullptr);
    }
}